// round 2
// baseline (speedup 1.0000x reference)
#include <cuda_runtime.h>
#include <cuda_bf16.h>

#define N_NODES 50000
#define N_EDGES 800000
#define DIM 128

// ---------------- device scratch (no allocations allowed) ----------------
__device__ float g_deg[N_NODES];
__device__ float g_dis[N_NODES];
__device__ int   g_cnt[N_NODES];
__device__ int   g_rowoff[N_NODES + 1];
__device__ int   g_cursor[N_NODES];
__device__ int   g_eid[N_EDGES];
__device__ float g_h[N_NODES * DIM];   // h = x @ W  (pre-aggregation features)
__device__ float g_t[N_NODES * DIM];   // layer-1 output (post relu)

// ---------------- setup kernels ----------------
__global__ void init_kernel() {
    int i = blockIdx.x * blockDim.x + threadIdx.x;
    if (i < N_NODES) { g_deg[i] = 0.f; g_cnt[i] = 0; }
}

__global__ void count_kernel(const int* __restrict__ ei,
                             const float* __restrict__ ew) {
    int e = blockIdx.x * blockDim.x + threadIdx.x;
    if (e < N_EDGES) {
        int d = ei[N_EDGES + e];        // dst
        atomicAdd(&g_deg[d], ew[e]);
        atomicAdd(&g_cnt[d], 1);
    }
}

__global__ void dis_kernel() {
    int i = blockIdx.x * blockDim.x + threadIdx.x;
    if (i < N_NODES) g_dis[i] = rsqrtf(g_deg[i] + 1.0f);
}

// single-block exclusive scan of g_cnt -> g_rowoff / g_cursor
__global__ void scan_kernel() {
    __shared__ int s[1024];
    const int t = threadIdx.x;
    const int CH = (N_NODES + 1023) / 1024;   // 49
    int beg = t * CH;
    int end = beg + CH; if (end > N_NODES) end = N_NODES;
    if (beg > N_NODES) beg = N_NODES;

    int sum = 0;
    for (int i = beg; i < end; i++) sum += g_cnt[i];
    s[t] = sum;
    __syncthreads();
    // inclusive Hillis-Steele scan
    for (int off = 1; off < 1024; off <<= 1) {
        int v = (t >= off) ? s[t - off] : 0;
        __syncthreads();
        s[t] += v;
        __syncthreads();
    }
    int run = (t > 0) ? s[t - 1] : 0;
    for (int i = beg; i < end; i++) {
        g_rowoff[i] = run;
        g_cursor[i] = run;
        run += g_cnt[i];
    }
    if (t == 1023) g_rowoff[N_NODES] = s[1023];
}

__global__ void fill_kernel(const int* __restrict__ ei) {
    int e = blockIdx.x * blockDim.x + threadIdx.x;
    if (e < N_EDGES) {
        int d = ei[N_EDGES + e];
        int pos = atomicAdd(&g_cursor[d], 1);
        g_eid[pos] = e;
    }
}

// ---------------- GEMM: C[M,128] = A[M,128] @ W[128,128] ----------------
// block = 128 threads (one per output column), computes TM=32 rows.
#define TM 32
__global__ __launch_bounds__(128) void gemm_kernel(const float* __restrict__ A,
                                                   const float* __restrict__ W,
                                                   float* __restrict__ C) {
    __shared__ float sA[DIM][TM + 4];   // transposed tile, +4 pad: low conflict
    const int r0 = blockIdx.x * TM;
    const int c = threadIdx.x;

    #pragma unroll
    for (int idx = threadIdx.x; idx < TM * DIM; idx += 128) {
        int r = idx >> 7;          // idx / 128
        int k = idx & 127;         // idx % 128
        float v = (r0 + r < N_NODES) ? A[(r0 + r) * DIM + k] : 0.f;
        sA[k][r] = v;
    }
    __syncthreads();

    float acc[TM];
    #pragma unroll
    for (int r = 0; r < TM; r++) acc[r] = 0.f;

    #pragma unroll 4
    for (int k = 0; k < DIM; k++) {
        float w = W[k * DIM + c];
        #pragma unroll
        for (int r = 0; r < TM; r++) acc[r] += sA[k][r] * w;
    }

    #pragma unroll
    for (int r = 0; r < TM; r++)
        if (r0 + r < N_NODES) C[(r0 + r) * DIM + c] = acc[r];
}

// ---------------- aggregation: one block (128 thr) per node ----------------
// out[i] = sum_{e: dst=i} h[src_e] * (dis[src]*ew*dis[i])  +  h[i]*dis[i]^2  + bias
__global__ __launch_bounds__(128) void agg_kernel(const float* __restrict__ h,
                                                  const float* __restrict__ bias,
                                                  float* __restrict__ out,
                                                  const int* __restrict__ ei,
                                                  const float* __restrict__ ew,
                                                  int do_relu) {
    const int i = blockIdx.x;
    const int c = threadIdx.x;
    const float di = g_dis[i];
    float acc = h[i * DIM + c] * di * di;

    const int beg = g_rowoff[i];
    const int end = g_rowoff[i + 1];

    __shared__ int   s_s[128];
    __shared__ float s_w[128];

    for (int base = beg; base < end; base += 128) {
        int n = end - base; if (n > 128) n = 128;
        if (c < n) {
            int e = g_eid[base + c];
            int s = ei[e];            // src
            s_s[c] = s;
            s_w[c] = g_dis[s] * ew[e] * di;
        }
        __syncthreads();
        for (int j = 0; j < n; j++)
            acc += h[s_s[j] * DIM + c] * s_w[j];
        __syncthreads();
    }

    acc += bias[c];
    if (do_relu) acc = fmaxf(acc, 0.f);
    out[i * DIM + c] = acc;
}

// ---------------- launch ----------------
extern "C" void kernel_launch(void* const* d_in, const int* in_sizes, int n_in,
                              void* d_out, int out_size) {
    const float* x  = (const float*)d_in[0];
    const int*   ei = (const int*)d_in[1];
    const float* ew = (const float*)d_in[2];
    const float* W1 = (const float*)d_in[3];
    const float* b1 = (const float*)d_in[4];
    const float* W2 = (const float*)d_in[5];
    const float* b2 = (const float*)d_in[6];
    float* out = (float*)d_out;

    float* h_buf; cudaGetSymbolAddress((void**)&h_buf, g_h);
    float* t_buf; cudaGetSymbolAddress((void**)&t_buf, g_t);

    const int NB_N = (N_NODES + 255) / 256;
    const int NB_E = (N_EDGES + 255) / 256;
    const int NB_G = (N_NODES + TM - 1) / TM;

    // graph structure setup (per launch; deterministic work)
    init_kernel<<<NB_N, 256>>>();
    count_kernel<<<NB_E, 256>>>(ei, ew);
    dis_kernel<<<NB_N, 256>>>();
    scan_kernel<<<1, 1024>>>();
    fill_kernel<<<NB_E, 256>>>(ei);

    // layer 1: h = x @ W1 ; t = relu(agg(h) + b1)
    gemm_kernel<<<NB_G, 128>>>(x, W1, h_buf);
    agg_kernel<<<N_NODES, 128>>>(h_buf, b1, t_buf, ei, ew, 1);

    // layer 2: h = t @ W2 ; out = agg(h) + b2
    gemm_kernel<<<NB_G, 128>>>(t_buf, W2, h_buf);
    agg_kernel<<<N_NODES, 128>>>(h_buf, b2, out, ei, ew, 0);
}

// round 3
// speedup vs baseline: 1.2856x; 1.2856x over previous
#include <cuda_runtime.h>
#include <cuda_bf16.h>

#define N_NODES 50000
#define N_EDGES 800000
#define DIM 128
#define NBS ((N_NODES + 255) / 256)   // 196 scan blocks

// ---------------- device scratch (no allocations allowed) ----------------
__device__ float g_deg[N_NODES];
__device__ float g_dis[N_NODES];
__device__ int   g_cnt[N_NODES];
__device__ int   g_pre[N_NODES];
__device__ int   g_bsum[NBS];
__device__ int   g_boff[NBS];
__device__ int   g_rowoff[N_NODES + 1];
__device__ int   g_cursor[N_NODES];
__device__ int   g_eid[N_EDGES];
__device__ float g_h[N_NODES * DIM];
__device__ float g_t[N_NODES * DIM];

// ---------------- setup kernels ----------------
__global__ void init_kernel() {
    int i = blockIdx.x * blockDim.x + threadIdx.x;
    if (i < N_NODES) { g_deg[i] = 0.f; g_cnt[i] = 0; }
}

__global__ void count_kernel(const int* __restrict__ ei,
                             const float* __restrict__ ew) {
    int e = blockIdx.x * blockDim.x + threadIdx.x;
    if (e < N_EDGES) {
        int d = ei[N_EDGES + e];        // dst
        atomicAdd(&g_deg[d], ew[e]);
        atomicAdd(&g_cnt[d], 1);
    }
}

// inclusive block scan (blockDim must be multiple of 32, <=1024)
__device__ __forceinline__ int block_scan_incl(int v, int* ws) {
    const int lane = threadIdx.x & 31;
    const int w = threadIdx.x >> 5;
    int incl = v;
    #pragma unroll
    for (int o = 1; o < 32; o <<= 1) {
        int t = __shfl_up_sync(0xffffffffu, incl, o);
        if (lane >= o) incl += t;
    }
    if (lane == 31) ws[w] = incl;
    __syncthreads();
    if (w == 0) {
        int nw = blockDim.x >> 5;
        int s = (lane < nw) ? ws[lane] : 0;
        #pragma unroll
        for (int o = 1; o < 32; o <<= 1) {
            int t = __shfl_up_sync(0xffffffffu, s, o);
            if (lane >= o) s += t;
        }
        if (lane < nw) ws[lane] = s;
    }
    __syncthreads();
    if (w > 0) incl += ws[w - 1];
    return incl;
}

// pass 1: per-block exclusive pre-scan + block sums; fused dis = rsqrt(deg+1)
__global__ __launch_bounds__(256) void scan1_kernel() {
    __shared__ int ws[8];
    int i = blockIdx.x * 256 + threadIdx.x;
    int v = (i < N_NODES) ? g_cnt[i] : 0;
    int incl = block_scan_incl(v, ws);
    if (i < N_NODES) g_pre[i] = incl - v;
    if (threadIdx.x == 255) g_bsum[blockIdx.x] = incl;
    if (i < N_NODES) g_dis[i] = rsqrtf(g_deg[i] + 1.0f);
}

// pass 2: scan the 196 block sums (single block)
__global__ __launch_bounds__(256) void scan2_kernel() {
    __shared__ int ws[8];
    int t = threadIdx.x;
    int v = (t < NBS) ? g_bsum[t] : 0;
    int incl = block_scan_incl(v, ws);
    if (t < NBS) g_boff[t] = incl - v;
}

// pass 3: add block offsets -> rowoff / cursor
__global__ __launch_bounds__(256) void scan3_kernel() {
    int i = blockIdx.x * 256 + threadIdx.x;
    if (i < N_NODES) {
        int r = g_pre[i] + g_boff[blockIdx.x];
        g_rowoff[i] = r;
        g_cursor[i] = r;
    }
    if (i == 0) g_rowoff[N_NODES] = N_EDGES;
}

__global__ void fill_kernel(const int* __restrict__ ei) {
    int e = blockIdx.x * blockDim.x + threadIdx.x;
    if (e < N_EDGES) {
        int d = ei[N_EDGES + e];
        int pos = atomicAdd(&g_cursor[d], 1);
        g_eid[pos] = e;
    }
}

// ---------------- GEMM: C[M,128] = A[M,128] @ W[128,128] ----------------
// 256 threads, 64-row tile. Thread (wy=tid/32, lane) computes 8 rows x 4 cols.
// sA row-major (coalesced STS, broadcast LDS); W streamed from L1 (64KB-resident).
#define MT 64
__global__ __launch_bounds__(256) void gemm_kernel(const float* __restrict__ A,
                                                   const float* __restrict__ W,
                                                   float* __restrict__ C) {
    __shared__ float sA[MT][DIM];     // 32 KB
    const int r0 = blockIdx.x * MT;
    const int tid = threadIdx.x;
    const int lane = tid & 31;
    const int wy = tid >> 5;          // 8 row-groups of 8 rows
    const int c0 = lane * 4;

    #pragma unroll
    for (int it = 0; it < 8; it++) {
        int idx = tid + it * 256;     // float4 index, 0..2047
        int r = idx >> 5;
        int k4 = idx & 31;
        float4 v = make_float4(0.f, 0.f, 0.f, 0.f);
        if (r0 + r < N_NODES)
            v = *(const float4*)(A + (size_t)(r0 + r) * DIM + k4 * 4);
        *(float4*)&sA[r][k4 * 4] = v;
    }
    __syncthreads();

    float acc[8][4];
    #pragma unroll
    for (int rr = 0; rr < 8; rr++)
        #pragma unroll
        for (int cc = 0; cc < 4; cc++) acc[rr][cc] = 0.f;

    #pragma unroll 4
    for (int k = 0; k < DIM; k++) {
        float4 wv = *(const float4*)(W + k * DIM + c0);
        #pragma unroll
        for (int rr = 0; rr < 8; rr++) {
            float a = sA[wy * 8 + rr][k];
            acc[rr][0] += a * wv.x;
            acc[rr][1] += a * wv.y;
            acc[rr][2] += a * wv.z;
            acc[rr][3] += a * wv.w;
        }
    }

    #pragma unroll
    for (int rr = 0; rr < 8; rr++) {
        int r = r0 + wy * 8 + rr;
        if (r < N_NODES)
            *(float4*)(C + (size_t)r * DIM + c0) =
                make_float4(acc[rr][0], acc[rr][1], acc[rr][2], acc[rr][3]);
    }
}

// ---------------- aggregation: one block (4 warps) per node ----------------
// Each warp reads full 512B h[src] rows (LDG.128/lane), warps split edges.
__global__ __launch_bounds__(128) void agg_kernel(const float* __restrict__ h,
                                                  const float* __restrict__ bias,
                                                  float* __restrict__ out,
                                                  const int* __restrict__ ei,
                                                  const float* __restrict__ ew,
                                                  int do_relu) {
    const int i = blockIdx.x;
    const int tid = threadIdx.x;
    const int w = tid >> 5;
    const int l = tid & 31;
    const float di = g_dis[i];

    const int beg = g_rowoff[i];
    const int end = g_rowoff[i + 1];

    __shared__ int   s_s[128];
    __shared__ float s_w[128];
    __shared__ float sred[3 * 128];

    float4 acc = make_float4(0.f, 0.f, 0.f, 0.f);

    for (int base = beg; base < end; base += 128) {
        int n = end - base;
        if (n > 128) n = 128;
        if (tid < n) {
            int e = g_eid[base + tid];
            int s = ei[e];
            s_s[tid] = s;
            s_w[tid] = g_dis[s] * ew[e] * di;
        }
        __syncthreads();
        for (int j = w; j < n; j += 4) {
            const float4 hv = *(const float4*)(h + (size_t)s_s[j] * DIM + l * 4);
            float wt = s_w[j];
            acc.x += hv.x * wt;
            acc.y += hv.y * wt;
            acc.z += hv.z * wt;
            acc.w += hv.w * wt;
        }
        __syncthreads();
    }

    if (w > 0)
        *(float4*)&sred[(w - 1) * 128 + l * 4] = acc;
    __syncthreads();

    if (w == 0) {
        #pragma unroll
        for (int p = 0; p < 3; p++) {
            float4 o = *(const float4*)&sred[p * 128 + l * 4];
            acc.x += o.x; acc.y += o.y; acc.z += o.z; acc.w += o.w;
        }
        const float dd = di * di;
        const float4 hi = *(const float4*)(h + (size_t)i * DIM + l * 4);
        const float4 bv = *(const float4*)(bias + l * 4);
        acc.x += hi.x * dd + bv.x;
        acc.y += hi.y * dd + bv.y;
        acc.z += hi.z * dd + bv.z;
        acc.w += hi.w * dd + bv.w;
        if (do_relu) {
            acc.x = fmaxf(acc.x, 0.f);
            acc.y = fmaxf(acc.y, 0.f);
            acc.z = fmaxf(acc.z, 0.f);
            acc.w = fmaxf(acc.w, 0.f);
        }
        *(float4*)(out + (size_t)i * DIM + l * 4) = acc;
    }
}

// ---------------- launch ----------------
extern "C" void kernel_launch(void* const* d_in, const int* in_sizes, int n_in,
                              void* d_out, int out_size) {
    const float* x  = (const float*)d_in[0];
    const int*   ei = (const int*)d_in[1];
    const float* ew = (const float*)d_in[2];
    const float* W1 = (const float*)d_in[3];
    const float* b1 = (const float*)d_in[4];
    const float* W2 = (const float*)d_in[5];
    const float* b2 = (const float*)d_in[6];
    float* out = (float*)d_out;

    float* h_buf; cudaGetSymbolAddress((void**)&h_buf, g_h);
    float* t_buf; cudaGetSymbolAddress((void**)&t_buf, g_t);

    const int NB_N = (N_NODES + 255) / 256;
    const int NB_E = (N_EDGES + 255) / 256;
    const int NB_G = (N_NODES + MT - 1) / MT;

    // graph structure setup
    init_kernel<<<NB_N, 256>>>();
    count_kernel<<<NB_E, 256>>>(ei, ew);
    scan1_kernel<<<NBS, 256>>>();      // also computes g_dis
    scan2_kernel<<<1, 256>>>();
    scan3_kernel<<<NBS, 256>>>();
    fill_kernel<<<NB_E, 256>>>(ei);

    // layer 1
    gemm_kernel<<<NB_G, 256>>>(x, W1, h_buf);
    agg_kernel<<<N_NODES, 128>>>(h_buf, b1, t_buf, ei, ew, 1);

    // layer 2
    gemm_kernel<<<NB_G, 256>>>(t_buf, W2, h_buf);
    agg_kernel<<<N_NODES, 128>>>(h_buf, b2, out, ei, ew, 0);
}